// round 7
// baseline (speedup 1.0000x reference)
#include <cuda_runtime.h>

// AttentionFusion: fused = sigmoid((x1-x2)@w) * x1 + (1-sigmoid) * x2
// N = 16384 rows, D = 2048 cols, fp32. Pure HBM streamer (402 MB min traffic).
//
// R5: persistent-CTA version of R4. Grid = 148*8 = 1184 resident CTAs, each
// loops over rows (stride gridDim.x). Same inner body as R4 (32 regs, occ 8,
// single barrier, __ldcs/__stcs). Gains: w loaded once per CTA (not 16384x),
// no wave transitions, no per-row CTA setup cost.

#define N_ROWS 16384
#define D_COLS 2048
#define THREADS 256
#define NWARPS (THREADS / 32)
#define GRID 1184   // 148 SMs * 8 CTAs

__global__ __launch_bounds__(THREADS, 8)
void attention_fusion_kernel(const float* __restrict__ x1,
                             const float* __restrict__ x2,
                             const float* __restrict__ w,
                             float* __restrict__ fused,
                             float* __restrict__ alpha) {
    const int tid  = threadIdx.x;
    const int lane = tid & 31;
    const int warp = tid >> 5;

    const float4* __restrict__ w4 = reinterpret_cast<const float4*>(w);
    // w held in registers for the whole persistent lifetime
    const float4 w0 = w4[tid];
    const float4 w1 = w4[tid + THREADS];

    __shared__ float warp_sums[NWARPS];

    for (int row = blockIdx.x; row < N_ROWS; row += GRID) {
        const float4* __restrict__ x1r =
            reinterpret_cast<const float4*>(x1) + (size_t)row * (D_COLS / 4);
        const float4* __restrict__ x2r =
            reinterpret_cast<const float4*>(x2) + (size_t)row * (D_COLS / 4);

        // Front-batched coalesced streaming loads (touched exactly once)
        float4 a0 = __ldcs(&x1r[tid]);
        float4 a1 = __ldcs(&x1r[tid + THREADS]);
        float4 b0 = __ldcs(&x2r[tid]);
        float4 b1 = __ldcs(&x2r[tid + THREADS]);

        // Partial of d = dot(x1 - x2, w)
        float d = (a0.x - b0.x) * w0.x;
        d = fmaf(a0.y - b0.y, w0.y, d);
        d = fmaf(a0.z - b0.z, w0.z, d);
        d = fmaf(a0.w - b0.w, w0.w, d);
        d = fmaf(a1.x - b1.x, w1.x, d);
        d = fmaf(a1.y - b1.y, w1.y, d);
        d = fmaf(a1.z - b1.z, w1.z, d);
        d = fmaf(a1.w - b1.w, w1.w, d);

        // Warp reduce
        #pragma unroll
        for (int off = 16; off > 0; off >>= 1)
            d += __shfl_xor_sync(0xFFFFFFFFu, d, off);

        if (lane == 0) warp_sums[warp] = d;
        __syncthreads();   // only barrier in the loop body

        // Every thread finishes the 8-way reduction itself (broadcast LDS)
        float v = warp_sums[0];
        #pragma unroll
        for (int i = 1; i < NWARPS; i++) v += warp_sums[i];

        const float al = 1.0f / (1.0f + expf(-v));   // sigmoid(s1 - s2)

        if (tid == 0) {
            alpha[(size_t)row * 2 + 0] = al;
            alpha[(size_t)row * 2 + 1] = 1.0f - al;
        }

        float4* __restrict__ outr =
            reinterpret_cast<float4*>(fused) + (size_t)row * (D_COLS / 4);

        float4 o0, o1;
        o0.x = fmaf(al, a0.x - b0.x, b0.x);   // al*a + (1-al)*b = al*(a-b) + b
        o0.y = fmaf(al, a0.y - b0.y, b0.y);
        o0.z = fmaf(al, a0.z - b0.z, b0.z);
        o0.w = fmaf(al, a0.w - b0.w, b0.w);
        o1.x = fmaf(al, a1.x - b1.x, b1.x);
        o1.y = fmaf(al, a1.y - b1.y, b1.y);
        o1.z = fmaf(al, a1.z - b1.z, b1.z);
        o1.w = fmaf(al, a1.w - b1.w, b1.w);

        __stcs(&outr[tid], o0);
        __stcs(&outr[tid + THREADS], o1);

        // Warp_sums reused next iteration; the __syncthreads at the top of the
        // next iteration's consumer path is this loop's barrier — but writes to
        // warp_sums happen before the next read only after a barrier:
        __syncthreads();
    }
}

extern "C" void kernel_launch(void* const* d_in, const int* in_sizes, int n_in,
                              void* d_out, int out_size) {
    const float* x1 = (const float*)d_in[0];
    const float* x2 = (const float*)d_in[1];
    const float* w  = (const float*)d_in[2];
    float* out = (float*)d_out;

    float* fused = out;                           // [N, D]
    float* alpha = out + (size_t)N_ROWS * D_COLS; // [N, 2]

    attention_fusion_kernel<<<GRID, THREADS>>>(x1, x2, w, fused, alpha);
}

// round 8
// speedup vs baseline: 1.0038x; 1.0038x over previous
#include <cuda_runtime.h>

// AttentionFusion: fused = sigmoid((x1-x2)@w) * x1 + (1-sigmoid) * x2
// N = 16384 rows, D = 2048 cols, fp32. Pure HBM streamer (402 MB min traffic).
//
// R5: persistent-CTA version of R4. Grid = 148*8 = 1184 resident CTAs, each
// loops over rows (stride gridDim.x). Same inner body as R4 (32 regs, occ 8,
// single barrier, __ldcs/__stcs). Gains: w loaded once per CTA (not 16384x),
// no wave transitions, no per-row CTA setup cost.

#define N_ROWS 16384
#define D_COLS 2048
#define THREADS 256
#define NWARPS (THREADS / 32)
#define GRID 1184   // 148 SMs * 8 CTAs

__global__ __launch_bounds__(THREADS, 8)
void attention_fusion_kernel(const float* __restrict__ x1,
                             const float* __restrict__ x2,
                             const float* __restrict__ w,
                             float* __restrict__ fused,
                             float* __restrict__ alpha) {
    const int tid  = threadIdx.x;
    const int lane = tid & 31;
    const int warp = tid >> 5;

    const float4* __restrict__ w4 = reinterpret_cast<const float4*>(w);
    // w held in registers for the whole persistent lifetime
    const float4 w0 = w4[tid];
    const float4 w1 = w4[tid + THREADS];

    __shared__ float warp_sums[NWARPS];

    for (int row = blockIdx.x; row < N_ROWS; row += GRID) {
        const float4* __restrict__ x1r =
            reinterpret_cast<const float4*>(x1) + (size_t)row * (D_COLS / 4);
        const float4* __restrict__ x2r =
            reinterpret_cast<const float4*>(x2) + (size_t)row * (D_COLS / 4);

        // Front-batched coalesced streaming loads (touched exactly once)
        float4 a0 = __ldcs(&x1r[tid]);
        float4 a1 = __ldcs(&x1r[tid + THREADS]);
        float4 b0 = __ldcs(&x2r[tid]);
        float4 b1 = __ldcs(&x2r[tid + THREADS]);

        // Partial of d = dot(x1 - x2, w)
        float d = (a0.x - b0.x) * w0.x;
        d = fmaf(a0.y - b0.y, w0.y, d);
        d = fmaf(a0.z - b0.z, w0.z, d);
        d = fmaf(a0.w - b0.w, w0.w, d);
        d = fmaf(a1.x - b1.x, w1.x, d);
        d = fmaf(a1.y - b1.y, w1.y, d);
        d = fmaf(a1.z - b1.z, w1.z, d);
        d = fmaf(a1.w - b1.w, w1.w, d);

        // Warp reduce
        #pragma unroll
        for (int off = 16; off > 0; off >>= 1)
            d += __shfl_xor_sync(0xFFFFFFFFu, d, off);

        if (lane == 0) warp_sums[warp] = d;
        __syncthreads();   // only barrier in the loop body

        // Every thread finishes the 8-way reduction itself (broadcast LDS)
        float v = warp_sums[0];
        #pragma unroll
        for (int i = 1; i < NWARPS; i++) v += warp_sums[i];

        const float al = 1.0f / (1.0f + expf(-v));   // sigmoid(s1 - s2)

        if (tid == 0) {
            alpha[(size_t)row * 2 + 0] = al;
            alpha[(size_t)row * 2 + 1] = 1.0f - al;
        }

        float4* __restrict__ outr =
            reinterpret_cast<float4*>(fused) + (size_t)row * (D_COLS / 4);

        float4 o0, o1;
        o0.x = fmaf(al, a0.x - b0.x, b0.x);   // al*a + (1-al)*b = al*(a-b) + b
        o0.y = fmaf(al, a0.y - b0.y, b0.y);
        o0.z = fmaf(al, a0.z - b0.z, b0.z);
        o0.w = fmaf(al, a0.w - b0.w, b0.w);
        o1.x = fmaf(al, a1.x - b1.x, b1.x);
        o1.y = fmaf(al, a1.y - b1.y, b1.y);
        o1.z = fmaf(al, a1.z - b1.z, b1.z);
        o1.w = fmaf(al, a1.w - b1.w, b1.w);

        __stcs(&outr[tid], o0);
        __stcs(&outr[tid + THREADS], o1);

        // Warp_sums reused next iteration; the __syncthreads at the top of the
        // next iteration's consumer path is this loop's barrier — but writes to
        // warp_sums happen before the next read only after a barrier:
        __syncthreads();
    }
}

extern "C" void kernel_launch(void* const* d_in, const int* in_sizes, int n_in,
                              void* d_out, int out_size) {
    const float* x1 = (const float*)d_in[0];
    const float* x2 = (const float*)d_in[1];
    const float* w  = (const float*)d_in[2];
    float* out = (float*)d_out;

    float* fused = out;                           // [N, D]
    float* alpha = out + (size_t)N_ROWS * D_COLS; // [N, 2]

    attention_fusion_kernel<<<GRID, THREADS>>>(x1, x2, w, fused, alpha);
}

// round 9
// speedup vs baseline: 1.0993x; 1.0952x over previous
#include <cuda_runtime.h>

// AttentionFusion: fused = sigmoid((x1-x2)@w) * x1 + (1-sigmoid) * x2
// N = 16384 rows, D = 2048 cols, fp32. Pure HBM streamer (~402 MB min traffic).
//
// R8: best structure (R0: one-shot CTA per row, 256 thr, occ 8/SM) + micro:
//  - single barrier, redundant per-thread finish of the 8-way reduce
//  - fast sigmoid: __expf + __frcp_rn (2 MUFU ops)
//  - alpha as one float2 store
//  - __ldcs on x1/x2 (touch-once), __stcs on fused; w default (L1-resident)
// R5 lesson: persistent CTAs serialize the load pipeline at barriers — one-shot
// CTA churn IS the software pipeline.

#define N_ROWS 16384
#define D_COLS 2048
#define THREADS 256
#define NWARPS (THREADS / 32)

__global__ __launch_bounds__(THREADS, 8)
void attention_fusion_kernel(const float* __restrict__ x1,
                             const float* __restrict__ x2,
                             const float* __restrict__ w,
                             float* __restrict__ fused,
                             float2* __restrict__ alpha) {
    const int row  = blockIdx.x;
    const int tid  = threadIdx.x;
    const int lane = tid & 31;
    const int warp = tid >> 5;

    const float4* __restrict__ x1r = reinterpret_cast<const float4*>(x1) + (size_t)row * (D_COLS / 4);
    const float4* __restrict__ x2r = reinterpret_cast<const float4*>(x2) + (size_t)row * (D_COLS / 4);
    const float4* __restrict__ w4  = reinterpret_cast<const float4*>(w);

    // Front-batched coalesced loads; x1/x2 evict-first (touched exactly once)
    float4 a0 = __ldcs(&x1r[tid]);
    float4 a1 = __ldcs(&x1r[tid + THREADS]);
    float4 b0 = __ldcs(&x2r[tid]);
    float4 b1 = __ldcs(&x2r[tid + THREADS]);
    float4 w0 = w4[tid];
    float4 w1 = w4[tid + THREADS];

    // Partial of d = dot(x1 - x2, w)
    float d = (a0.x - b0.x) * w0.x;
    d = fmaf(a0.y - b0.y, w0.y, d);
    d = fmaf(a0.z - b0.z, w0.z, d);
    d = fmaf(a0.w - b0.w, w0.w, d);
    d = fmaf(a1.x - b1.x, w1.x, d);
    d = fmaf(a1.y - b1.y, w1.y, d);
    d = fmaf(a1.z - b1.z, w1.z, d);
    d = fmaf(a1.w - b1.w, w1.w, d);

    // Warp reduce
    #pragma unroll
    for (int off = 16; off > 0; off >>= 1)
        d += __shfl_xor_sync(0xFFFFFFFFu, d, off);

    __shared__ float warp_sums[NWARPS];
    if (lane == 0) warp_sums[warp] = d;
    __syncthreads();   // the only barrier

    // Every thread finishes the reduction itself (conflict-free broadcast LDS)
    float v = warp_sums[0];
    #pragma unroll
    for (int i = 1; i < NWARPS; i++) v += warp_sums[i];

    // Fast sigmoid: 2 MUFU ops; tolerance is 1e-3, __expf rel err ~1e-7 here
    const float al = __frcp_rn(1.0f + __expf(-v));

    if (tid == 0) {
        alpha[row] = make_float2(al, 1.0f - al);
    }

    float4* __restrict__ outr = reinterpret_cast<float4*>(fused) + (size_t)row * (D_COLS / 4);

    float4 o0, o1;
    o0.x = fmaf(al, a0.x - b0.x, b0.x);   // al*a + (1-al)*b = al*(a-b) + b
    o0.y = fmaf(al, a0.y - b0.y, b0.y);
    o0.z = fmaf(al, a0.z - b0.z, b0.z);
    o0.w = fmaf(al, a0.w - b0.w, b0.w);
    o1.x = fmaf(al, a1.x - b1.x, b1.x);
    o1.y = fmaf(al, a1.y - b1.y, b1.y);
    o1.z = fmaf(al, a1.z - b1.z, b1.z);
    o1.w = fmaf(al, a1.w - b1.w, b1.w);

    __stcs(&outr[tid], o0);
    __stcs(&outr[tid + THREADS], o1);
}

extern "C" void kernel_launch(void* const* d_in, const int* in_sizes, int n_in,
                              void* d_out, int out_size) {
    const float* x1 = (const float*)d_in[0];
    const float* x2 = (const float*)d_in[1];
    const float* w  = (const float*)d_in[2];
    float* out = (float*)d_out;

    float*  fused = out;                                             // [N, D]
    float2* alpha = reinterpret_cast<float2*>(out + (size_t)N_ROWS * D_COLS); // [N, 2]

    attention_fusion_kernel<<<N_ROWS, THREADS>>>(x1, x2, w, fused, alpha);
}

// round 10
// speedup vs baseline: 1.1039x; 1.0041x over previous
#include <cuda_runtime.h>

// AttentionFusion: fused = sigmoid((x1-x2)@w) * x1 + (1-sigmoid) * x2
// N = 16384 rows, D = 2048 cols, fp32. Pure HBM streamer (~402 MB min traffic).
//
// R8: best structure (R0: one-shot CTA per row, 256 thr, occ 8/SM) + micro:
//  - single barrier, redundant per-thread finish of the 8-way reduce
//  - fast sigmoid: __expf + __frcp_rn (2 MUFU ops)
//  - alpha as one float2 store
//  - __ldcs on x1/x2 (touch-once), __stcs on fused; w default (L1-resident)
// R5 lesson: persistent CTAs serialize the load pipeline at barriers — one-shot
// CTA churn IS the software pipeline.

#define N_ROWS 16384
#define D_COLS 2048
#define THREADS 256
#define NWARPS (THREADS / 32)

__global__ __launch_bounds__(THREADS, 8)
void attention_fusion_kernel(const float* __restrict__ x1,
                             const float* __restrict__ x2,
                             const float* __restrict__ w,
                             float* __restrict__ fused,
                             float2* __restrict__ alpha) {
    const int row  = blockIdx.x;
    const int tid  = threadIdx.x;
    const int lane = tid & 31;
    const int warp = tid >> 5;

    const float4* __restrict__ x1r = reinterpret_cast<const float4*>(x1) + (size_t)row * (D_COLS / 4);
    const float4* __restrict__ x2r = reinterpret_cast<const float4*>(x2) + (size_t)row * (D_COLS / 4);
    const float4* __restrict__ w4  = reinterpret_cast<const float4*>(w);

    // Front-batched coalesced loads; x1/x2 evict-first (touched exactly once)
    float4 a0 = __ldcs(&x1r[tid]);
    float4 a1 = __ldcs(&x1r[tid + THREADS]);
    float4 b0 = __ldcs(&x2r[tid]);
    float4 b1 = __ldcs(&x2r[tid + THREADS]);
    float4 w0 = w4[tid];
    float4 w1 = w4[tid + THREADS];

    // Partial of d = dot(x1 - x2, w)
    float d = (a0.x - b0.x) * w0.x;
    d = fmaf(a0.y - b0.y, w0.y, d);
    d = fmaf(a0.z - b0.z, w0.z, d);
    d = fmaf(a0.w - b0.w, w0.w, d);
    d = fmaf(a1.x - b1.x, w1.x, d);
    d = fmaf(a1.y - b1.y, w1.y, d);
    d = fmaf(a1.z - b1.z, w1.z, d);
    d = fmaf(a1.w - b1.w, w1.w, d);

    // Warp reduce
    #pragma unroll
    for (int off = 16; off > 0; off >>= 1)
        d += __shfl_xor_sync(0xFFFFFFFFu, d, off);

    __shared__ float warp_sums[NWARPS];
    if (lane == 0) warp_sums[warp] = d;
    __syncthreads();   // the only barrier

    // Every thread finishes the reduction itself (conflict-free broadcast LDS)
    float v = warp_sums[0];
    #pragma unroll
    for (int i = 1; i < NWARPS; i++) v += warp_sums[i];

    // Fast sigmoid: 2 MUFU ops; tolerance is 1e-3, __expf rel err ~1e-7 here
    const float al = __frcp_rn(1.0f + __expf(-v));

    if (tid == 0) {
        alpha[row] = make_float2(al, 1.0f - al);
    }

    float4* __restrict__ outr = reinterpret_cast<float4*>(fused) + (size_t)row * (D_COLS / 4);

    float4 o0, o1;
    o0.x = fmaf(al, a0.x - b0.x, b0.x);   // al*a + (1-al)*b = al*(a-b) + b
    o0.y = fmaf(al, a0.y - b0.y, b0.y);
    o0.z = fmaf(al, a0.z - b0.z, b0.z);
    o0.w = fmaf(al, a0.w - b0.w, b0.w);
    o1.x = fmaf(al, a1.x - b1.x, b1.x);
    o1.y = fmaf(al, a1.y - b1.y, b1.y);
    o1.z = fmaf(al, a1.z - b1.z, b1.z);
    o1.w = fmaf(al, a1.w - b1.w, b1.w);

    __stcs(&outr[tid], o0);
    __stcs(&outr[tid + THREADS], o1);
}

extern "C" void kernel_launch(void* const* d_in, const int* in_sizes, int n_in,
                              void* d_out, int out_size) {
    const float* x1 = (const float*)d_in[0];
    const float* x2 = (const float*)d_in[1];
    const float* w  = (const float*)d_in[2];
    float* out = (float*)d_out;

    float*  fused = out;                                             // [N, D]
    float2* alpha = reinterpret_cast<float2*>(out + (size_t)N_ROWS * D_COLS); // [N, 2]

    attention_fusion_kernel<<<N_ROWS, THREADS>>>(x1, x2, w, fused, alpha);
}

// round 11
// speedup vs baseline: 1.1044x; 1.0005x over previous
#include <cuda_runtime.h>

// AttentionFusion: fused = sigmoid((x1-x2)@w) * x1 + (1-sigmoid) * x2
// N = 16384 rows, D = 2048 cols, fp32. Pure HBM streamer (~402 MB min traffic).
//
// R8: best structure (R0: one-shot CTA per row, 256 thr, occ 8/SM) + micro:
//  - single barrier, redundant per-thread finish of the 8-way reduce
//  - fast sigmoid: __expf + __frcp_rn (2 MUFU ops)
//  - alpha as one float2 store
//  - __ldcs on x1/x2 (touch-once), __stcs on fused; w default (L1-resident)
// R5 lesson: persistent CTAs serialize the load pipeline at barriers — one-shot
// CTA churn IS the software pipeline.

#define N_ROWS 16384
#define D_COLS 2048
#define THREADS 256
#define NWARPS (THREADS / 32)

__global__ __launch_bounds__(THREADS, 8)
void attention_fusion_kernel(const float* __restrict__ x1,
                             const float* __restrict__ x2,
                             const float* __restrict__ w,
                             float* __restrict__ fused,
                             float2* __restrict__ alpha) {
    const int row  = blockIdx.x;
    const int tid  = threadIdx.x;
    const int lane = tid & 31;
    const int warp = tid >> 5;

    const float4* __restrict__ x1r = reinterpret_cast<const float4*>(x1) + (size_t)row * (D_COLS / 4);
    const float4* __restrict__ x2r = reinterpret_cast<const float4*>(x2) + (size_t)row * (D_COLS / 4);
    const float4* __restrict__ w4  = reinterpret_cast<const float4*>(w);

    // Front-batched coalesced loads; x1/x2 evict-first (touched exactly once)
    float4 a0 = __ldcs(&x1r[tid]);
    float4 a1 = __ldcs(&x1r[tid + THREADS]);
    float4 b0 = __ldcs(&x2r[tid]);
    float4 b1 = __ldcs(&x2r[tid + THREADS]);
    float4 w0 = w4[tid];
    float4 w1 = w4[tid + THREADS];

    // Partial of d = dot(x1 - x2, w)
    float d = (a0.x - b0.x) * w0.x;
    d = fmaf(a0.y - b0.y, w0.y, d);
    d = fmaf(a0.z - b0.z, w0.z, d);
    d = fmaf(a0.w - b0.w, w0.w, d);
    d = fmaf(a1.x - b1.x, w1.x, d);
    d = fmaf(a1.y - b1.y, w1.y, d);
    d = fmaf(a1.z - b1.z, w1.z, d);
    d = fmaf(a1.w - b1.w, w1.w, d);

    // Warp reduce
    #pragma unroll
    for (int off = 16; off > 0; off >>= 1)
        d += __shfl_xor_sync(0xFFFFFFFFu, d, off);

    __shared__ float warp_sums[NWARPS];
    if (lane == 0) warp_sums[warp] = d;
    __syncthreads();   // the only barrier

    // Every thread finishes the reduction itself (conflict-free broadcast LDS)
    float v = warp_sums[0];
    #pragma unroll
    for (int i = 1; i < NWARPS; i++) v += warp_sums[i];

    // Fast sigmoid: 2 MUFU ops; tolerance is 1e-3, __expf rel err ~1e-7 here
    const float al = __frcp_rn(1.0f + __expf(-v));

    if (tid == 0) {
        alpha[row] = make_float2(al, 1.0f - al);
    }

    float4* __restrict__ outr = reinterpret_cast<float4*>(fused) + (size_t)row * (D_COLS / 4);

    float4 o0, o1;
    o0.x = fmaf(al, a0.x - b0.x, b0.x);   // al*a + (1-al)*b = al*(a-b) + b
    o0.y = fmaf(al, a0.y - b0.y, b0.y);
    o0.z = fmaf(al, a0.z - b0.z, b0.z);
    o0.w = fmaf(al, a0.w - b0.w, b0.w);
    o1.x = fmaf(al, a1.x - b1.x, b1.x);
    o1.y = fmaf(al, a1.y - b1.y, b1.y);
    o1.z = fmaf(al, a1.z - b1.z, b1.z);
    o1.w = fmaf(al, a1.w - b1.w, b1.w);

    __stcs(&outr[tid], o0);
    __stcs(&outr[tid + THREADS], o1);
}

extern "C" void kernel_launch(void* const* d_in, const int* in_sizes, int n_in,
                              void* d_out, int out_size) {
    const float* x1 = (const float*)d_in[0];
    const float* x2 = (const float*)d_in[1];
    const float* w  = (const float*)d_in[2];
    float* out = (float*)d_out;

    float*  fused = out;                                             // [N, D]
    float2* alpha = reinterpret_cast<float2*>(out + (size_t)N_ROWS * D_COLS); // [N, 2]

    attention_fusion_kernel<<<N_ROWS, THREADS>>>(x1, x2, w, fused, alpha);
}